// round 11
// baseline (speedup 1.0000x reference)
#include <cuda_runtime.h>
#include <cuda_fp16.h>

#define NN 50000
#define EE 500000
#define GG 128
#define NCHUNK ((NN + 255) / 256)   // 196

struct __align__(8) Edge { int s; float w; };

// ---------------- scratch ----------------
__device__ float g_deg[NN];
__device__ float g_dinv[NN];
__device__ int   g_count[NN];
__device__ int   g_rs0[NN];
__device__ int   g_rowstart[NN + 1];
__device__ int   g_cursor[NN];
__device__ int   g_part[NCHUNK];
__device__ Edge  g_edge[EE];

__device__ __half g_Xh[NN * 160];
__device__ __half g_T1[NN * 160];
__device__ __half g_T2[NN * 160];
__device__ __half g_H1[NN * 128];
__device__ __half g_H2[NN * 64];
__device__ float  g_pool[GG * 32];
__device__ float  g_cntg[GG];

__device__ unsigned g_barcnt;
__device__ volatile unsigned g_barflag;
__device__ unsigned g_done;

// ---------------- grid barrier (blocks guaranteed co-resident via occupancy API) ----------------
__device__ __forceinline__ void gridsync(unsigned target) {
    __threadfence();
    __syncthreads();
    if (threadIdx.x == 0) {
        if (atomicAdd(&g_barcnt, 1) == gridDim.x - 1) {
            g_barcnt = 0;
            __threadfence();
            g_barflag = target;
        } else {
            while (g_barflag != target) __nanosleep(64);
        }
    }
    __syncthreads();
}

// ---------------- persistent preprocessing (R7 proven phase code) ----------------
__global__ void __launch_bounds__(256, 6)
preproc_kernel(const float* __restrict__ x, const int* __restrict__ src,
               const int* __restrict__ dst, const float* __restrict__ ea,
               const int* __restrict__ batch) {
    __shared__ int scan[256];
    int tid = threadIdx.x;
    int gid = blockIdx.x * 256 + tid;
    int gsz = gridDim.x * 256;
    unsigned base = g_barflag;

    // Phase A: zero + x -> half
    for (int i = gid; i < NN; i += gsz) { g_deg[i] = 0.f; g_count[i] = 0; }
    for (int i = gid; i < GG * 32; i += gsz) g_pool[i] = 0.f;
    for (int i = gid; i < GG; i += gsz) g_cntg[i] = 0.f;
    if (gid == 0) g_done = 0;
    for (long i = gid; i < (long)NN * 40; i += gsz) {
        float4 v = ((const float4*)x)[i];
        uint2 r;
        *(__half2*)&r.x = __float22half2_rn(make_float2(v.x, v.y));
        *(__half2*)&r.y = __float22half2_rn(make_float2(v.z, v.w));
        ((uint2*)g_Xh)[i] = r;
    }
    gridsync(base + 1);

    // Phase B: degree + in-count
    for (int e = gid; e < EE; e += gsz) {
        atomicAdd(&g_deg[src[e]], ea[e]);
        atomicAdd(&g_count[dst[e]], 1);
    }
    gridsync(base + 2);

    // Phase C: chunk-local scans + dinv
    for (int c = blockIdx.x; c < NCHUNK; c += gridDim.x) {
        int i = c * 256 + tid;
        int v = (i < NN) ? g_count[i] : 0;
        scan[tid] = v;
        __syncthreads();
        for (int off = 1; off < 256; off <<= 1) {
            int a = (tid >= off) ? scan[tid - off] : 0;
            __syncthreads();
            scan[tid] += a;
            __syncthreads();
        }
        if (i < NN) g_rs0[i] = scan[tid] - v;
        if (tid == 255) g_part[c] = scan[255];
        __syncthreads();
    }
    for (int i = gid; i < NN; i += gsz) {
        float d = g_deg[i];
        g_dinv[i] = (d > 0.f) ? rsqrtf(d) : 0.f;
    }
    gridsync(base + 3);

    // Phase D: scan chunk sums (block 0)
    if (blockIdx.x == 0) {
        int v = (tid < NCHUNK) ? g_part[tid] : 0;
        scan[tid] = v;
        __syncthreads();
        for (int off = 1; off < 256; off <<= 1) {
            int a = (tid >= off) ? scan[tid - off] : 0;
            __syncthreads();
            scan[tid] += a;
            __syncthreads();
        }
        if (tid < NCHUNK) g_part[tid] = scan[tid] - v;
    }
    gridsync(base + 4);

    // Phase E: finalize rowstart/cursor + per-graph counts
    for (int i = gid; i < NN; i += gsz) {
        int v = g_rs0[i] + g_part[i >> 8];
        g_rowstart[i] = v;
        g_cursor[i] = v;
        atomicAdd(&g_cntg[batch[i]], 1.f);
    }
    if (gid == 0) g_rowstart[NN] = EE;
    gridsync(base + 5);

    // Phase F: scatter edges into CSR
    for (int e = gid; e < EE; e += gsz) {
        int s = src[e], d = dst[e];
        float w = -g_dinv[s] * ea[e] * g_dinv[d];
        int pos = atomicAdd(&g_cursor[d], 1);
        Edge eg; eg.s = s; eg.w = w;
        g_edge[pos] = eg;
    }
}

// ---------------- half helpers ----------------
struct Acc4 { float2 a, b; };
__device__ __forceinline__ Acc4 acc4z() { Acc4 r; r.a = make_float2(0.f,0.f); r.b = r.a; return r; }
__device__ __forceinline__ void fmah4(Acc4& A, float w, uint2 u) {
    float2 f0 = __half22float2(*reinterpret_cast<__half2*>(&u.x));
    float2 f1 = __half22float2(*reinterpret_cast<__half2*>(&u.y));
    A.a.x = fmaf(w, f0.x, A.a.x); A.a.y = fmaf(w, f0.y, A.a.y);
    A.b.x = fmaf(w, f1.x, A.b.x); A.b.y = fmaf(w, f1.y, A.b.y);
}
__device__ __forceinline__ void addh4(Acc4& A, Acc4 B) {
    A.a.x += B.a.x; A.a.y += B.a.y; A.b.x += B.b.x; A.b.y += B.b.y;
}
__device__ __forceinline__ void s2sh4(Acc4& A, uint2 t) {   // A = 2A - t
    float2 f0 = __half22float2(*reinterpret_cast<__half2*>(&t.x));
    float2 f1 = __half22float2(*reinterpret_cast<__half2*>(&t.y));
    A.a.x = fmaf(2.f, A.a.x, -f0.x); A.a.y = fmaf(2.f, A.a.y, -f0.y);
    A.b.x = fmaf(2.f, A.b.x, -f1.x); A.b.y = fmaf(2.f, A.b.y, -f1.y);
}
__device__ __forceinline__ uint2 packh4(Acc4 A) {
    uint2 r;
    *(__half2*)&r.x = __float22half2_rn(A.a);
    *(__half2*)&r.y = __float22half2_rn(A.b);
    return r;
}

// ---------------- prop bodies (R10 proven inner loops, node-strided) ----------------
template <bool SECOND>
__device__ __forceinline__ void prop160_body(const __half* __restrict__ X,
                                             const __half* __restrict__ T0,
                                             __half* __restrict__ out) {
    int lane = threadIdx.x & 31;
    int nw = gridDim.x << 3;
    for (int node = (blockIdx.x << 3) + (threadIdx.x >> 5); node < NN; node += nw) {
        int s = g_rowstart[node], e = g_rowstart[node + 1];
        const uint2* X4 = (const uint2*)X;
        Acc4 a0 = acc4z(), a1 = a0, b0 = a0, b1 = a0;
        int j = s;
        for (; j + 1 < e; j += 2) {
            Edge e0 = g_edge[j], e1 = g_edge[j+1];
            long r0 = (long)e0.s * 40, r1 = (long)e1.s * 40;
            fmah4(a0, e0.w, X4[r0 + lane]);
            fmah4(a1, e1.w, X4[r1 + lane]);
            if (lane < 8) {
                fmah4(b0, e0.w, X4[r0 + 32 + lane]);
                fmah4(b1, e1.w, X4[r1 + 32 + lane]);
            }
        }
        if (j < e) {
            Edge e0 = g_edge[j];
            long r0 = (long)e0.s * 40;
            fmah4(a0, e0.w, X4[r0 + lane]);
            if (lane < 8) fmah4(b0, e0.w, X4[r0 + 32 + lane]);
        }
        addh4(a0, a1);
        addh4(b0, b1);
        long o = (long)node * 40;
        const uint2* T04 = (const uint2*)T0;
        if (SECOND) {
            s2sh4(a0, T04[o + lane]);
            if (lane < 8) s2sh4(b0, T04[o + 32 + lane]);
        }
        ((uint2*)out)[o + lane] = packh4(a0);
        if (lane < 8) ((uint2*)out)[o + 32 + lane] = packh4(b0);
    }
}

template <bool SECOND>
__device__ __forceinline__ void prop128_body(const __half* __restrict__ X,
                                             const __half* __restrict__ T0,
                                             __half* __restrict__ out) {
    int lane = threadIdx.x & 31;
    int nw = gridDim.x << 3;
    for (int node = (blockIdx.x << 3) + (threadIdx.x >> 5); node < NN; node += nw) {
        int s = g_rowstart[node], e = g_rowstart[node + 1];
        const uint2* X4 = (const uint2*)X;
        Acc4 a0 = acc4z(), a1 = a0;
        int j = s;
        for (; j + 1 < e; j += 2) {
            Edge e0 = g_edge[j], e1 = g_edge[j+1];
            fmah4(a0, e0.w, X4[(long)e0.s * 32 + lane]);
            fmah4(a1, e1.w, X4[(long)e1.s * 32 + lane]);
        }
        if (j < e) {
            Edge e0 = g_edge[j];
            fmah4(a0, e0.w, X4[(long)e0.s * 32 + lane]);
        }
        addh4(a0, a1);
        long o = (long)node * 32 + lane;
        if (SECOND) s2sh4(a0, ((const uint2*)T0)[o]);
        ((uint2*)out)[o] = packh4(a0);
    }
}

template <bool SECOND>
__device__ __forceinline__ void prop64_body(const __half* __restrict__ X,
                                            const __half* __restrict__ T0,
                                            __half* __restrict__ out) {
    int lane = threadIdx.x & 31;
    int nw = gridDim.x << 3;
    for (int node = (blockIdx.x << 3) + (threadIdx.x >> 5); node < NN; node += nw) {
        int s = g_rowstart[node], e = g_rowstart[node + 1];
        const __half2* X2 = (const __half2*)X;
        float2 a0 = make_float2(0.f,0.f), a1 = a0;
        int j = s;
        for (; j + 1 < e; j += 2) {
            Edge e0 = g_edge[j], e1 = g_edge[j+1];
            float2 f0 = __half22float2(X2[(long)e0.s * 32 + lane]);
            float2 f1 = __half22float2(X2[(long)e1.s * 32 + lane]);
            a0.x = fmaf(e0.w, f0.x, a0.x); a0.y = fmaf(e0.w, f0.y, a0.y);
            a1.x = fmaf(e1.w, f1.x, a1.x); a1.y = fmaf(e1.w, f1.y, a1.y);
        }
        if (j < e) {
            Edge e0 = g_edge[j];
            float2 f0 = __half22float2(X2[(long)e0.s * 32 + lane]);
            a0.x = fmaf(e0.w, f0.x, a0.x); a0.y = fmaf(e0.w, f0.y, a0.y);
        }
        a0.x += a1.x; a0.y += a1.y;
        long o = (long)node * 32 + lane;
        if (SECOND) {
            float2 t = __half22float2(((const __half2*)T0)[o]);
            a0.x = fmaf(2.f, a0.x, -t.x);
            a0.y = fmaf(2.f, a0.y, -t.y);
        }
        ((__half2*)out)[o] = __float22half2_rn(a0);
    }
}

// ---------------- prop-pair persistent kernels (one internal grid sync) ----------------
__global__ void __launch_bounds__(256, 5)
prop160pair(const __half* __restrict__ X) {
    unsigned base = g_barflag;
    prop160_body<false>(X, nullptr, g_T1);
    gridsync(base + 1);
    prop160_body<true>(g_T1, X, g_T2);
}

__global__ void __launch_bounds__(256, 5)
prop128pair(const __half* __restrict__ X) {
    unsigned base = g_barflag;
    prop128_body<false>(X, nullptr, g_T1);
    gridsync(base + 1);
    prop128_body<true>(g_T1, X, g_T2);
}

__global__ void __launch_bounds__(256, 5)
prop64pair(const __half* __restrict__ X) {
    unsigned base = g_barflag;
    prop64_body<false>(X, nullptr, g_T1);
    gridsync(base + 1);
    prop64_body<true>(g_T1, X, g_T2);
}

// ---------------- fp16 m16n8k16 MMA helpers ----------------
__device__ __forceinline__ void mma_f16(float* c, const unsigned* a, unsigned b0, unsigned b1) {
    asm volatile(
        "mma.sync.aligned.m16n8k16.row.col.f32.f16.f16.f32 "
        "{%0,%1,%2,%3}, {%4,%5,%6,%7}, {%8,%9}, {%0,%1,%2,%3};"
        : "+f"(c[0]), "+f"(c[1]), "+f"(c[2]), "+f"(c[3])
        : "r"(a[0]), "r"(a[1]), "r"(a[2]), "r"(a[3]), "r"(b0), "r"(b1));
}
__device__ __forceinline__ unsigned pack2h(float lo, float hi) {
    __half2 h = __float22half2_rn(make_float2(lo, hi));
    return *reinterpret_cast<unsigned*>(&h);
}

// ---------------- fp16 fused 3-term GEMM (R10 proven); POOL also runs final linear in last block ----------------
template <int FIN, int FOUT, bool POOL>
__global__ void __launch_bounds__(256, 4)
gemm3_mma(const __half* __restrict__ A0, const __half* __restrict__ A1,
          const __half* __restrict__ A2, const float* __restrict__ W,
          const float* __restrict__ bias, __half* __restrict__ out,
          const int* __restrict__ batch,
          const float* __restrict__ Wl, const float* __restrict__ bl,
          float* __restrict__ outF) {
    constexpr int BM = 64, BK = 32;
    constexpr int ASTR = 20;
    constexpr int BSTR = FOUT + 8;
    constexpr int NCH = 3 * FIN / BK;
    constexpr int NI = FOUT / 16;
    constexpr int BSLOT = 16 * (FOUT / 4);
    __shared__ unsigned As2[BM * ASTR];
    __shared__ unsigned Bs2[16 * BSTR];

    int tid = threadIdx.x;
    int wp = tid >> 5, lane = tid & 31;
    int wy = wp >> 1, wx = wp & 1;
    int ly = lane >> 2, lx = lane & 3;
    int row0 = blockIdx.x * BM;

    float acc[NI][4];
#pragma unroll
    for (int ni = 0; ni < NI; ni++)
#pragma unroll
        for (int i = 0; i < 4; i++) acc[ni][i] = 0.f;

    for (int c = 0; c < NCH; c++) {
        int k0 = c * BK;
        const __half* A = (k0 < FIN) ? A0 : ((k0 < 2 * FIN) ? A1 : A2);
        int kk = k0 % FIN;
        {
            int r = tid >> 2, u = tid & 3;
            int grow = row0 + r;
            uint4 v = make_uint4(0u, 0u, 0u, 0u);
            if (grow < NN) v = *(const uint4*)&A[(long)grow * FIN + kk + u * 8];
            *(uint4*)&As2[r * ASTR + u * 4] = v;
        }
#pragma unroll
        for (int i = 0; i < (BSLOT + 255) / 256; i++) {
            int idx = i * 256 + tid;
            if (BSLOT >= 256 * (i + 1) || idx < BSLOT) {
                int kp = idx / (FOUT / 4);
                int c4 = (idx % (FOUT / 4)) * 4;
                const float* w0 = &W[(long)(k0 + 2 * kp) * FOUT + c4];
                float4 va = *(const float4*)w0;
                float4 vb = *(const float4*)(w0 + FOUT);
                uint4 u;
                u.x = pack2h(va.x, vb.x);
                u.y = pack2h(va.y, vb.y);
                u.z = pack2h(va.z, vb.z);
                u.w = pack2h(va.w, vb.w);
                *(uint4*)&Bs2[kp * BSTR + c4] = u;
            }
        }
        __syncthreads();

#pragma unroll
        for (int cc = 0; cc < 2; cc++) {
            unsigned a[4];
            int ar = wy * 16 + ly;
            int ak = cc * 8 + lx;
            a[0] = As2[ar * ASTR + ak];
            a[1] = As2[(ar + 8) * ASTR + ak];
            a[2] = As2[ar * ASTR + ak + 4];
            a[3] = As2[(ar + 8) * ASTR + ak + 4];
#pragma unroll
            for (int ni = 0; ni < NI; ni++) {
                int bn = wx * (FOUT / 2) + ni * 8 + ly;
                unsigned b0 = Bs2[(cc * 8 + lx) * BSTR + bn];
                unsigned b1 = Bs2[(cc * 8 + 4 + lx) * BSTR + bn];
                mma_f16(acc[ni], a, b0, b1);
            }
        }
        __syncthreads();
    }

    // epilogue
    int r0 = row0 + wy * 16 + ly;
#pragma unroll
    for (int ni = 0; ni < NI; ni++) {
        int col = wx * (FOUT / 2) + ni * 8 + lx * 2;
        float bv0 = bias[col], bv1 = bias[col + 1];
        float v00 = fmaxf(acc[ni][0] + bv0, 0.f);
        float v01 = fmaxf(acc[ni][1] + bv1, 0.f);
        float v10 = fmaxf(acc[ni][2] + bv0, 0.f);
        float v11 = fmaxf(acc[ni][3] + bv1, 0.f);
        if (!POOL) {
            if (r0 < NN)
                *(__half2*)&out[(long)r0 * FOUT + col] = __float22half2_rn(make_float2(v00, v01));
            if (r0 + 8 < NN)
                *(__half2*)&out[(long)(r0 + 8) * FOUT + col] = __float22half2_rn(make_float2(v10, v11));
        } else {
            if (r0 < NN) {
                int g = batch[r0];
                atomicAdd(&g_pool[g * 32 + col], v00);
                atomicAdd(&g_pool[g * 32 + col + 1], v01);
            }
            if (r0 + 8 < NN) {
                int g = batch[r0 + 8];
                atomicAdd(&g_pool[g * 32 + col], v10);
                atomicAdd(&g_pool[g * 32 + col + 1], v11);
            }
        }
    }

    // POOL: last-arriving block computes the final linear
    if (POOL) {
        __shared__ int slast;
        __threadfence();
        if (tid == 0) slast = (atomicAdd(&g_done, 1) == gridDim.x - 1) ? 1 : 0;
        __syncthreads();
        if (slast && tid < GG * 2) {
            int g = tid >> 1, cc = tid & 1;
            float cnt = fmaxf(g_cntg[g], 1.f);
            float inv = 1.f / cnt;
            float s = bl[cc];
#pragma unroll
            for (int f = 0; f < 32; f++) s += (g_pool[g * 32 + f] * inv) * Wl[f * 2 + cc];
            outF[g * 2 + cc] = s;
        }
    }
}

// ---------------- driver ----------------
extern "C" void kernel_launch(void* const* d_in, const int* in_sizes, int n_in,
                              void* d_out, int out_size) {
    const float* x     = (const float*)d_in[0];
    const int*   ei    = (const int*)d_in[1];
    const float* ea    = (const float*)d_in[2];
    const int*   batch = (const int*)d_in[3];
    const float* W1 = (const float*)d_in[4];
    const float* b1 = (const float*)d_in[5];
    const float* W2 = (const float*)d_in[6];
    const float* b2 = (const float*)d_in[7];
    const float* W3 = (const float*)d_in[8];
    const float* b3 = (const float*)d_in[9];
    const float* Wl = (const float*)d_in[10];
    const float* bl = (const float*)d_in[11];
    float* out = (float*)d_out;

    const int* src = ei;
    const int* dst = ei + EE;

    __half *Xh, *T1, *T2, *H1, *H2;
    cudaGetSymbolAddress((void**)&Xh, g_Xh);
    cudaGetSymbolAddress((void**)&T1, g_T1);
    cudaGetSymbolAddress((void**)&T2, g_T2);
    cudaGetSymbolAddress((void**)&H1, g_H1);
    cudaGetSymbolAddress((void**)&H2, g_H2);

    int dev = 0, nsm = 148;
    cudaGetDevice(&dev);
    cudaDeviceGetAttribute(&nsm, cudaDevAttrMultiProcessorCount, dev);

    int oP = 1, o160 = 1, o128 = 1, o64 = 1;
    cudaOccupancyMaxActiveBlocksPerMultiprocessor(&oP,   preproc_kernel, 256, 0);
    cudaOccupancyMaxActiveBlocksPerMultiprocessor(&o160, prop160pair,    256, 0);
    cudaOccupancyMaxActiveBlocksPerMultiprocessor(&o128, prop128pair,    256, 0);
    cudaOccupancyMaxActiveBlocksPerMultiprocessor(&o64,  prop64pair,     256, 0);
    if (oP < 1) oP = 1;
    if (o160 < 1) o160 = 1;
    if (o128 < 1) o128 = 1;
    if (o64 < 1) o64 = 1;

    int gb = (NN + 63) / 64;   // gemm grid (BM=64)

    // Preprocessing (persistent, 5 internal grid syncs)
    preproc_kernel<<<nsm * oP, 256>>>(x, src, dst, ea, batch);

    // Layer 1: 160 -> 128
    prop160pair<<<nsm * o160, 256>>>(Xh);
    gemm3_mma<160, 128, false><<<gb, 256>>>(Xh, T1, T2, W1, b1, H1, nullptr,
                                            nullptr, nullptr, nullptr);

    // Layer 2: 128 -> 64
    prop128pair<<<nsm * o128, 256>>>(H1);
    gemm3_mma<128, 64, false><<<gb, 256>>>(H1, T1, T2, W2, b2, H2, nullptr,
                                           nullptr, nullptr, nullptr);

    // Layer 3: 64 -> 32 (pool + final linear fused)
    prop64pair<<<nsm * o64, 256>>>(H2);
    gemm3_mma<64, 32, true><<<gb, 256>>>(H2, T1, T2, W3, b3, nullptr, batch,
                                         Wl, bl, out);
}

// round 13
// speedup vs baseline: 1.0583x; 1.0583x over previous
#include <cuda_runtime.h>
#include <cuda_fp16.h>

#define NN 50000
#define EE 500000
#define GG 128
#define SCAN_B 512
#define NBLK ((NN + SCAN_B - 1) / SCAN_B)   // 98

struct __align__(8) Edge { int s; float w; };

// ---------------- scratch ----------------
__device__ float g_deg[NN];
__device__ float g_dinv[NN];
__device__ int   g_count[NN];
__device__ int   g_rowstart[NN + 1];
__device__ int   g_cursor[NN];
__device__ int   g_part[NBLK];
__device__ Edge  g_edge[EE];

__device__ __half g_Xh[NN * 160];
__device__ __half g_T1[NN * 160];
__device__ __half g_T2[NN * 160];
__device__ __half g_H1[NN * 128];
__device__ __half g_H2[NN * 64];
__device__ float  g_pool[GG * 32];
__device__ float  g_cntg[GG];

// Pre-converted weights: [kpair][col] half2, kpair = rows (2k,2k+1) of W
#define W1P (240 * 128)   // (3*160/2) x 128
#define W2P (192 * 64)    // (3*128/2) x 64   <- FIXED (was 96*64)
#define W3P (96 * 32)     // (3*64/2)  x 32
__device__ unsigned g_W1h[W1P];
__device__ unsigned g_W2h[W2P];
__device__ unsigned g_W3h[W3P];

__device__ __forceinline__ unsigned pack2h(float lo, float hi) {
    __half2 h = __float22half2_rn(make_float2(lo, hi));
    return *reinterpret_cast<unsigned*>(&h);
}

// ---------------- preprocessing ----------------
// zero + x->half + weight pre-conversion (independent index ranges)
__global__ void zero_conv_kernel(const float* __restrict__ x, const float* __restrict__ W1,
                                 const float* __restrict__ W2, const float* __restrict__ W3) {
    long i = (long)blockIdx.x * blockDim.x + threadIdx.x;
    if (i < NN) { g_deg[i] = 0.f; g_count[i] = 0; }
    if (i < GG * 32) g_pool[i] = 0.f;
    if (i < GG) g_cntg[i] = 0.f;
    if (i < (long)NN * 40) {
        float4 v = ((const float4*)x)[i];
        uint2 r;
        *(__half2*)&r.x = __float22half2_rn(make_float2(v.x, v.y));
        *(__half2*)&r.y = __float22half2_rn(make_float2(v.z, v.w));
        ((uint2*)g_Xh)[i] = r;
    }
    if (i < W1P) {
        int kp = (int)i >> 7, col = (int)i & 127;
        g_W1h[i] = pack2h(W1[(2 * kp) * 128 + col], W1[(2 * kp + 1) * 128 + col]);
    }
    if (i < W2P) {
        int kp = (int)i >> 6, col = (int)i & 63;
        g_W2h[i] = pack2h(W2[(2 * kp) * 64 + col], W2[(2 * kp + 1) * 64 + col]);
    }
    if (i < W3P) {
        int kp = (int)i >> 5, col = (int)i & 31;
        g_W3h[i] = pack2h(W3[(2 * kp) * 32 + col], W3[(2 * kp + 1) * 32 + col]);
    }
}

__global__ void edge_deg_kernel(const int* __restrict__ src, const int* __restrict__ dst,
                                const float* __restrict__ ea) {
    int e = blockIdx.x * blockDim.x + threadIdx.x;
    if (e >= EE) return;
    atomicAdd(&g_deg[src[e]], ea[e]);
    atomicAdd(&g_count[dst[e]], 1);
}

__global__ void scan1_kernel() {
    __shared__ int s[SCAN_B];
    int t = threadIdx.x;
    int i = blockIdx.x * SCAN_B + t;
    int v = (i < NN) ? g_count[i] : 0;
    s[t] = v;
    __syncthreads();
    for (int off = 1; off < SCAN_B; off <<= 1) {
        int add = (t >= off) ? s[t - off] : 0;
        __syncthreads();
        s[t] += add;
        __syncthreads();
    }
    if (i < NN) g_rowstart[i] = s[t] - v;
    if (t == SCAN_B - 1) g_part[blockIdx.x] = s[t];
}

__global__ void scan2_kernel() {
    __shared__ int s[128];
    int t = threadIdx.x;
    int v = (t < NBLK) ? g_part[t] : 0;
    s[t] = v;
    __syncthreads();
    for (int off = 1; off < 128; off <<= 1) {
        int a = (t >= off) ? s[t - off] : 0;
        __syncthreads();
        s[t] += a;
        __syncthreads();
    }
    if (t < NBLK) g_part[t] = s[t] - v;
}

__global__ void scan3_kernel(const int* __restrict__ batch) {
    int i = blockIdx.x * blockDim.x + threadIdx.x;
    if (i < NN) {
        int v = g_rowstart[i] + g_part[i / SCAN_B];
        g_rowstart[i] = v;
        g_cursor[i] = v;
        float d = g_deg[i];
        g_dinv[i] = (d > 0.f) ? rsqrtf(d) : 0.f;
        atomicAdd(&g_cntg[batch[i]], 1.f);
    }
    if (i == 0) g_rowstart[NN] = EE;
}

__global__ void edge_scatter_kernel(const int* __restrict__ src, const int* __restrict__ dst,
                                    const float* __restrict__ ea) {
    int e = blockIdx.x * blockDim.x + threadIdx.x;
    if (e >= EE) return;
    int s = src[e], d = dst[e];
    float w = -g_dinv[s] * ea[e] * g_dinv[d];
    int pos = atomicAdd(&g_cursor[d], 1);
    Edge eg; eg.s = s; eg.w = w;
    g_edge[pos] = eg;
}

// ---------------- half helpers ----------------
struct Acc4 { float2 a, b; };
__device__ __forceinline__ Acc4 acc4z() { Acc4 r; r.a = make_float2(0.f,0.f); r.b = r.a; return r; }
__device__ __forceinline__ void fmah4(Acc4& A, float w, uint2 u) {
    float2 f0 = __half22float2(*reinterpret_cast<__half2*>(&u.x));
    float2 f1 = __half22float2(*reinterpret_cast<__half2*>(&u.y));
    A.a.x = fmaf(w, f0.x, A.a.x); A.a.y = fmaf(w, f0.y, A.a.y);
    A.b.x = fmaf(w, f1.x, A.b.x); A.b.y = fmaf(w, f1.y, A.b.y);
}
__device__ __forceinline__ void addh4(Acc4& A, Acc4 B) {
    A.a.x += B.a.x; A.a.y += B.a.y; A.b.x += B.b.x; A.b.y += B.b.y;
}
__device__ __forceinline__ void s2sh4(Acc4& A, uint2 t) {   // A = 2A - t
    float2 f0 = __half22float2(*reinterpret_cast<__half2*>(&t.x));
    float2 f1 = __half22float2(*reinterpret_cast<__half2*>(&t.y));
    A.a.x = fmaf(2.f, A.a.x, -f0.x); A.a.y = fmaf(2.f, A.a.y, -f0.y);
    A.b.x = fmaf(2.f, A.b.x, -f1.x); A.b.y = fmaf(2.f, A.b.y, -f1.y);
}
__device__ __forceinline__ uint2 packh4(Acc4 A) {
    uint2 r;
    *(__half2*)&r.x = __float22half2_rn(A.a);
    *(__half2*)&r.y = __float22half2_rn(A.b);
    return r;
}

// ---------------- sparse propagate: warp per node, 2-way ILP, 32-bit indexing ----------------
template <bool SECOND>
__global__ void __launch_bounds__(256, 5)
prop160h(const __half* __restrict__ X, const __half* __restrict__ T0, __half* __restrict__ out) {
    int node = (blockIdx.x << 3) + (threadIdx.x >> 5);
    if (node >= NN) return;
    unsigned lane = threadIdx.x & 31;
    int s = g_rowstart[node], e = g_rowstart[node + 1];
    const uint2* X4 = (const uint2*)X;
    Acc4 a0 = acc4z(), a1 = a0, b0 = a0, b1 = a0;
    int j = s;
    for (; j + 1 < e; j += 2) {
        Edge e0 = g_edge[j], e1 = g_edge[j+1];
        unsigned r0 = (unsigned)e0.s * 40u + lane, r1 = (unsigned)e1.s * 40u + lane;
        fmah4(a0, e0.w, X4[r0]);
        fmah4(a1, e1.w, X4[r1]);
        if (lane < 8) {
            fmah4(b0, e0.w, X4[r0 + 32u]);
            fmah4(b1, e1.w, X4[r1 + 32u]);
        }
    }
    if (j < e) {
        Edge e0 = g_edge[j];
        unsigned r0 = (unsigned)e0.s * 40u + lane;
        fmah4(a0, e0.w, X4[r0]);
        if (lane < 8) fmah4(b0, e0.w, X4[r0 + 32u]);
    }
    addh4(a0, a1);
    addh4(b0, b1);
    unsigned o = (unsigned)node * 40u + lane;
    const uint2* T04 = (const uint2*)T0;
    if (SECOND) {
        s2sh4(a0, T04[o]);
        if (lane < 8) s2sh4(b0, T04[o + 32u]);
    }
    ((uint2*)out)[o] = packh4(a0);
    if (lane < 8) ((uint2*)out)[o + 32u] = packh4(b0);
}

template <bool SECOND>
__global__ void __launch_bounds__(256, 5)
prop128h(const __half* __restrict__ X, const __half* __restrict__ T0, __half* __restrict__ out) {
    int node = (blockIdx.x << 3) + (threadIdx.x >> 5);
    if (node >= NN) return;
    unsigned lane = threadIdx.x & 31;
    int s = g_rowstart[node], e = g_rowstart[node + 1];
    const uint2* X4 = (const uint2*)X;
    Acc4 a0 = acc4z(), a1 = a0;
    int j = s;
    for (; j + 1 < e; j += 2) {
        Edge e0 = g_edge[j], e1 = g_edge[j+1];
        fmah4(a0, e0.w, X4[(unsigned)e0.s * 32u + lane]);
        fmah4(a1, e1.w, X4[(unsigned)e1.s * 32u + lane]);
    }
    if (j < e) {
        Edge e0 = g_edge[j];
        fmah4(a0, e0.w, X4[(unsigned)e0.s * 32u + lane]);
    }
    addh4(a0, a1);
    unsigned o = (unsigned)node * 32u + lane;
    if (SECOND) s2sh4(a0, ((const uint2*)T0)[o]);
    ((uint2*)out)[o] = packh4(a0);
}

template <bool SECOND>
__global__ void __launch_bounds__(256, 5)
prop64h(const __half* __restrict__ X, const __half* __restrict__ T0, __half* __restrict__ out) {
    int node = (blockIdx.x << 3) + (threadIdx.x >> 5);
    if (node >= NN) return;
    unsigned lane = threadIdx.x & 31;
    int s = g_rowstart[node], e = g_rowstart[node + 1];
    const __half2* X2 = (const __half2*)X;
    float2 a0 = make_float2(0.f,0.f), a1 = a0;
    int j = s;
    for (; j + 1 < e; j += 2) {
        Edge e0 = g_edge[j], e1 = g_edge[j+1];
        float2 f0 = __half22float2(X2[(unsigned)e0.s * 32u + lane]);
        float2 f1 = __half22float2(X2[(unsigned)e1.s * 32u + lane]);
        a0.x = fmaf(e0.w, f0.x, a0.x); a0.y = fmaf(e0.w, f0.y, a0.y);
        a1.x = fmaf(e1.w, f1.x, a1.x); a1.y = fmaf(e1.w, f1.y, a1.y);
    }
    if (j < e) {
        Edge e0 = g_edge[j];
        float2 f0 = __half22float2(X2[(unsigned)e0.s * 32u + lane]);
        a0.x = fmaf(e0.w, f0.x, a0.x); a0.y = fmaf(e0.w, f0.y, a0.y);
    }
    a0.x += a1.x; a0.y += a1.y;
    unsigned o = (unsigned)node * 32u + lane;
    if (SECOND) {
        float2 t = __half22float2(((const __half2*)T0)[o]);
        a0.x = fmaf(2.f, a0.x, -t.x);
        a0.y = fmaf(2.f, a0.y, -t.y);
    }
    ((__half2*)out)[o] = __float22half2_rn(a0);
}

// ---------------- fp16 m16n8k16 MMA helpers ----------------
__device__ __forceinline__ void mma_f16(float* c, const unsigned* a, unsigned b0, unsigned b1) {
    asm volatile(
        "mma.sync.aligned.m16n8k16.row.col.f32.f16.f16.f32 "
        "{%0,%1,%2,%3}, {%4,%5,%6,%7}, {%8,%9}, {%0,%1,%2,%3};"
        : "+f"(c[0]), "+f"(c[1]), "+f"(c[2]), "+f"(c[3])
        : "r"(a[0]), "r"(a[1]), "r"(a[2]), "r"(a[3]), "r"(b0), "r"(b1));
}

// ---------------- fp16 fused 3-term GEMM: BM=64, BK=32, pre-converted half weights ----------------
// out = relu([A0|A1|A2] @ W + bias); POOL: atomicAdd into g_pool by batch instead.
template <int FIN, int FOUT, bool POOL>
__global__ void __launch_bounds__(256, 4)
gemm3_mma(const __half* __restrict__ A0, const __half* __restrict__ A1,
          const __half* __restrict__ A2, const unsigned* __restrict__ Wh,
          const float* __restrict__ bias, __half* __restrict__ out,
          const int* __restrict__ batch) {
    constexpr int BM = 64, BK = 32;
    constexpr int ASTR = 20;            // half2 units/row (16 data + 4 pad)
    constexpr int BSTR = FOUT + 8;      // half2 units per kpair row (== 8 mod 32)
    constexpr int NCH = 3 * FIN / BK;
    constexpr int NI = FOUT / 16;       // n8 tiles per warp (warp tile 16 x FOUT/2)
    constexpr int BQ = 16 * (FOUT / 4); // uint4 copies per chunk (16 kpairs x FOUT/4)
    __shared__ unsigned As2[BM * ASTR];
    __shared__ unsigned Bs2[16 * BSTR];

    int tid = threadIdx.x;
    int wp = tid >> 5, lane = tid & 31;
    int wy = wp >> 1, wx = wp & 1;
    int ly = lane >> 2, lx = lane & 3;
    int row0 = blockIdx.x * BM;

    float acc[NI][4];
#pragma unroll
    for (int ni = 0; ni < NI; ni++)
#pragma unroll
        for (int i = 0; i < 4; i++) acc[ni][i] = 0.f;

    for (int c = 0; c < NCH; c++) {
        int k0 = c * BK;
        const __half* A = (k0 < FIN) ? A0 : ((k0 < 2 * FIN) ? A1 : A2);
        int kk = k0 % FIN;
        // A tile: 64 rows x 4 uint4, 1/thread, direct copy.
        {
            int r = tid >> 2, u = tid & 3;
            int grow = row0 + r;
            uint4 v = make_uint4(0u, 0u, 0u, 0u);
            if (grow < NN) v = *(const uint4*)&A[(unsigned)grow * FIN + kk + u * 8];
            *(uint4*)&As2[r * ASTR + u * 4] = v;
        }
        // B tile: direct uint4 copy from pre-converted Wh. 16 kpairs per chunk.
#pragma unroll
        for (int i = 0; i < (BQ + 255) / 256; i++) {
            int idx = i * 256 + tid;
            if (BQ >= 256 * (i + 1) || idx < BQ) {
                int kp = idx / (FOUT / 4);
                int c4 = (idx % (FOUT / 4)) * 4;
                uint4 u = *(const uint4*)&Wh[(unsigned)(c * 16 + kp) * FOUT + c4];
                *(uint4*)&Bs2[kp * BSTR + c4] = u;
            }
        }
        __syncthreads();

#pragma unroll
        for (int cc = 0; cc < 2; cc++) {
            unsigned a[4];
            int ar = wy * 16 + ly;
            int ak = cc * 8 + lx;
            a[0] = As2[ar * ASTR + ak];
            a[1] = As2[(ar + 8) * ASTR + ak];
            a[2] = As2[ar * ASTR + ak + 4];
            a[3] = As2[(ar + 8) * ASTR + ak + 4];
#pragma unroll
            for (int ni = 0; ni < NI; ni++) {
                int bn = wx * (FOUT / 2) + ni * 8 + ly;
                unsigned b0 = Bs2[(cc * 8 + lx) * BSTR + bn];
                unsigned b1 = Bs2[(cc * 8 + 4 + lx) * BSTR + bn];
                mma_f16(acc[ni], a, b0, b1);
            }
        }
        __syncthreads();
    }

    // epilogue
    int r0 = row0 + wy * 16 + ly;
#pragma unroll
    for (int ni = 0; ni < NI; ni++) {
        int col = wx * (FOUT / 2) + ni * 8 + lx * 2;
        float bv0 = bias[col], bv1 = bias[col + 1];
        float v00 = fmaxf(acc[ni][0] + bv0, 0.f);
        float v01 = fmaxf(acc[ni][1] + bv1, 0.f);
        float v10 = fmaxf(acc[ni][2] + bv0, 0.f);
        float v11 = fmaxf(acc[ni][3] + bv1, 0.f);
        if (!POOL) {
            if (r0 < NN)
                *(__half2*)&out[(unsigned)r0 * FOUT + col] = __float22half2_rn(make_float2(v00, v01));
            if (r0 + 8 < NN)
                *(__half2*)&out[(unsigned)(r0 + 8) * FOUT + col] = __float22half2_rn(make_float2(v10, v11));
        } else {
            if (r0 < NN) {
                int g = batch[r0];
                atomicAdd(&g_pool[g * 32 + col], v00);
                atomicAdd(&g_pool[g * 32 + col + 1], v01);
            }
            if (r0 + 8 < NN) {
                int g = batch[r0 + 8];
                atomicAdd(&g_pool[g * 32 + col], v10);
                atomicAdd(&g_pool[g * 32 + col + 1], v11);
            }
        }
    }
}

// ---------------- final linear ----------------
__global__ void final_kernel(const float* __restrict__ Wl, const float* __restrict__ bl,
                             float* __restrict__ out) {
    int t = threadIdx.x;
    if (t >= GG * 2) return;
    int g = t >> 1, c = t & 1;
    float cnt = fmaxf(g_cntg[g], 1.f);
    float inv = 1.f / cnt;
    float s = bl[c];
#pragma unroll
    for (int f = 0; f < 32; f++) s += (g_pool[g * 32 + f] * inv) * Wl[f * 2 + c];
    out[g * 2 + c] = s;
}

// ---------------- driver ----------------
extern "C" void kernel_launch(void* const* d_in, const int* in_sizes, int n_in,
                              void* d_out, int out_size) {
    const float* x     = (const float*)d_in[0];
    const int*   ei    = (const int*)d_in[1];
    const float* ea    = (const float*)d_in[2];
    const int*   batch = (const int*)d_in[3];
    const float* W1 = (const float*)d_in[4];
    const float* b1 = (const float*)d_in[5];
    const float* W2 = (const float*)d_in[6];
    const float* b2 = (const float*)d_in[7];
    const float* W3 = (const float*)d_in[8];
    const float* b3 = (const float*)d_in[9];
    const float* Wl = (const float*)d_in[10];
    const float* bl = (const float*)d_in[11];
    float* out = (float*)d_out;

    const int* src = ei;
    const int* dst = ei + EE;

    __half *Xh, *T1, *T2, *H1, *H2;
    unsigned *W1h, *W2h, *W3h;
    cudaGetSymbolAddress((void**)&Xh, g_Xh);
    cudaGetSymbolAddress((void**)&T1, g_T1);
    cudaGetSymbolAddress((void**)&T2, g_T2);
    cudaGetSymbolAddress((void**)&H1, g_H1);
    cudaGetSymbolAddress((void**)&H2, g_H2);
    cudaGetSymbolAddress((void**)&W1h, g_W1h);
    cudaGetSymbolAddress((void**)&W2h, g_W2h);
    cudaGetSymbolAddress((void**)&W3h, g_W3h);

    int eb = (EE + 255) / 256;
    int pb = (NN + 7) / 8;             // warp-per-node prop grid
    int gb = (NN + 63) / 64;           // gemm grid (BM=64)
    int zb = ((NN * 40) + 255) / 256;  // zero+convert grid
    int nb = (NN + 255) / 256;

    zero_conv_kernel<<<zb, 256>>>(x, W1, W2, W3);
    edge_deg_kernel<<<eb, 256>>>(src, dst, ea);
    scan1_kernel<<<NBLK, SCAN_B>>>();
    scan2_kernel<<<1, 128>>>();
    scan3_kernel<<<nb, 256>>>(batch);
    edge_scatter_kernel<<<eb, 256>>>(src, dst, ea);

    // Layer 1: 160 -> 128
    prop160h<false><<<pb, 256>>>(Xh, nullptr, T1);
    prop160h<true ><<<pb, 256>>>(T1, Xh, T2);
    gemm3_mma<160, 128, false><<<gb, 256>>>(Xh, T1, T2, W1h, b1, H1, nullptr);

    // Layer 2: 128 -> 64
    prop128h<false><<<pb, 256>>>(H1, nullptr, T1);
    prop128h<true ><<<pb, 256>>>(T1, H1, T2);
    gemm3_mma<128, 64, false><<<gb, 256>>>(H1, T1, T2, W2h, b2, H2, nullptr);

    // Layer 3: 64 -> 32  (pooling fused into epilogue)
    prop64h<false><<<pb, 256>>>(H2, nullptr, T1);
    prop64h<true ><<<pb, 256>>>(T1, H2, T2);
    gemm3_mma<64, 32, true><<<gb, 256>>>(H2, T1, T2, W3h, b3, nullptr, batch);

    // Final linear
    final_kernel<<<1, 256>>>(Wl, bl, out);
}